// round 7
// baseline (speedup 1.0000x reference)
#include <cuda_runtime.h>
#include <cuda_bf16.h>
#include <cstdint>

#define BB 256
#define TT 64
#define IN 512
#define HH 1024
#define NS (BB*TT)   /* 16384 samples, s = b*TT + t (natural x order) */
#define CAP 8192     /* event capacity per batch (≈300x expected) */

// ---------------- scratch (__device__ globals; no allocs allowed) ----------------
__device__ unsigned int g_mask0[NS*32];        // layer-0 spike bitmasks [s][32]
__device__ unsigned int g_mask1[NS*32];
__device__ unsigned int g_ev[(size_t)BB*CAP];  // per-b event list (t<<10|k), t-sorted
__device__ int g_nev[BB];
__device__ __nv_bfloat16 g_Abf[(size_t)NS*IN]; // input spikes as bf16 [s][i]
__device__ __nv_bfloat16 g_W0hi[HH*IN];        // bf16 split of W0 [h][i]
__device__ __nv_bfloat16 g_W0lo[HH*IN];
__device__ float g_W1t[HH*HH];                 // W1^T : [1024][1024]

// ================= helpers =======================================================
__device__ __forceinline__ uint32_t smem_u32(const void* p) {
    uint32_t a;
    asm("{ .reg .u64 t; cvta.to.shared.u64 t, %1; cvt.u32.u64 %0, t; }" : "=r"(a) : "l"(p));
    return a;
}
__device__ __forceinline__ void cp_async16(uint32_t dst, const void* src) {
    asm volatile("cp.async.cg.shared.global [%0], [%1], 16;" :: "r"(dst), "l"(src));
}
__device__ __forceinline__ uint32_t lds32(uint32_t a) {
    uint32_t v;
    asm volatile("ld.shared.b32 %0, [%1];" : "=r"(v) : "r"(a));
    return v;
}
__device__ __forceinline__ void mma16816(float* c, const uint32_t* a, const uint32_t* b) {
    asm volatile(
        "mma.sync.aligned.m16n8k16.row.col.f32.bf16.bf16.f32 "
        "{%0,%1,%2,%3}, {%4,%5,%6,%7}, {%8,%9}, {%0,%1,%2,%3};"
        : "+f"(c[0]), "+f"(c[1]), "+f"(c[2]), "+f"(c[3])
        : "r"(a[0]), "r"(a[1]), "r"(a[2]), "r"(a[3]), "r"(b[0]), "r"(b[1]));
}

// ================= prep kernels ==================================================
// x [B][T][I] fp32 -> bf16, same linear order (s = b*TT + t is x's natural order)
__global__ void k_convA(const float* __restrict__ x, __nv_bfloat16* __restrict__ A) {
    size_t p = (size_t)blockIdx.x * blockDim.x + threadIdx.x;   // NS*IN/4 threads
    float4 v = *(const float4*)(x + p * 4);
    __nv_bfloat162 lo = __floats2bfloat162_rn(v.x, v.y);
    __nv_bfloat162 hi = __floats2bfloat162_rn(v.z, v.w);
    uint2 o; o.x = *(uint32_t*)&lo; o.y = *(uint32_t*)&hi;
    *(uint2*)(A + p * 4) = o;
}
// W0 fp32 -> (hi, lo) bf16 split
__global__ void k_splitW(const float* __restrict__ W, __nv_bfloat16* __restrict__ Whi,
                         __nv_bfloat16* __restrict__ Wlo, int n) {
    int e = blockIdx.x * blockDim.x + threadIdx.x;
    if (e >= n) return;
    float w = W[e];
    __nv_bfloat16 h = __float2bfloat16(w);
    __nv_bfloat16 l = __float2bfloat16(w - __bfloat162float(h));
    Whi[e] = h; Wlo[e] = l;
}
// transpose: in[R][C] -> out[C][R]  (for W1)
__global__ void k_transpose(const float* __restrict__ in, float* __restrict__ out,
                            int R, int C) {
    __shared__ float tl[32][33];
    int c0 = blockIdx.x * 32, r0 = blockIdx.y * 32;
    int x = c0 + threadIdx.x;
    for (int j = 0; j < 32; j += 8) {
        int y = r0 + threadIdx.y + j;
        if (y < R && x < C) tl[threadIdx.y + j][threadIdx.x] = in[(size_t)y * C + x];
    }
    __syncthreads();
    int x2 = r0 + threadIdx.x;
    for (int j = 0; j < 32; j += 8) {
        int y2 = c0 + threadIdx.y + j;
        if (y2 < C && x2 < R) out[(size_t)y2 * R + x2] = tl[threadIdx.x][threadIdx.y + j];
    }
}

// ================= layer 0: fused HMMA GEMM + leaky scan =========================
// CTA tile 128x128 (M rows = 2 batches x 64 timesteps), 8 warps, K chunks of 64,
// double-buffered cp.async, split-bf16 (8 chunks W0hi + 8 W0lo), fp32 accum.
// Epilogue: D -> smem, per-(b,h) in-register scan over t, write spk0/mem0/mask0.
#define KCH   64
#define LDAH  72
#define ROWB  (LDAH*2)                   /* 144 bytes */
#define TILEB (128*ROWB)                 /* 18432 B per operand tile */
#define BUFB  (2*TILEB)                  /* 36864 B per buffer */
#define EPAD  132                        /* padded epilogue row (floats) */

extern __shared__ char dynsm[];

__global__ __launch_bounds__(256, 2)
void k_gemm0_fused(const __nv_bfloat16* __restrict__ A,
                   const __nv_bfloat16* __restrict__ Whi,
                   const __nv_bfloat16* __restrict__ Wlo,
                   const float* __restrict__ thr_p,
                   float* __restrict__ spk0, float* __restrict__ mem0,
                   unsigned int* __restrict__ mask0) {
    int tid = threadIdx.x;
    int wid = tid >> 5, lane = tid & 31;
    int g = lane >> 2, tig = lane & 3;
    int wm = wid & 3, wn = wid >> 2;             // warp grid 4(M) x 2(N)
    int m0 = blockIdx.x * 128;
    int n0 = blockIdx.y * 128;

    uint32_t smb = smem_u32(dynsm);

    float acc[2][8][4];
#pragma unroll
    for (int mi = 0; mi < 2; ++mi)
#pragma unroll
        for (int ni = 0; ni < 8; ++ni)
#pragma unroll
            for (int r = 0; r < 4; ++r) acc[mi][ni][r] = 0.0f;

    auto stage = [&](int c, int buf) {
        const __nv_bfloat16* Wsrc = (c < 8) ? Whi : Wlo;
        int kcol = (c & 7) * KCH;
        uint32_t abase = smb + buf * BUFB;
        uint32_t bbase = abase + TILEB;
#pragma unroll
        for (int j = 0; j < 4; ++j) {
            int id = tid + j * 256;
            int row = id >> 3, seg = id & 7;
            cp_async16(abase + row * ROWB + seg * 16,
                       A + (size_t)(m0 + row) * IN + kcol + seg * 8);
            cp_async16(bbase + row * ROWB + seg * 16,
                       Wsrc + (size_t)(n0 + row) * IN + kcol + seg * 8);
        }
        asm volatile("cp.async.commit_group;" ::: "memory");
    };

    stage(0, 0);

    for (int c = 0; c < 16; ++c) {
        int buf = c & 1;
        if (c + 1 < 16) {
            stage(c + 1, buf ^ 1);
            asm volatile("cp.async.wait_group 1;" ::: "memory");
        } else {
            asm volatile("cp.async.wait_group 0;" ::: "memory");
        }
        __syncthreads();

        uint32_t abase = smb + buf * BUFB;
        uint32_t bbase = abase + TILEB;
#pragma unroll
        for (int kk = 0; kk < 4; ++kk) {
            int ko = kk * 16;
            uint32_t a[2][4], b[8][2];
#pragma unroll
            for (int mi = 0; mi < 2; ++mi) {
                uint32_t base = abase + (uint32_t)(wm * 32 + mi * 16 + g) * ROWB
                              + (uint32_t)(ko + tig * 2) * 2;
                a[mi][0] = lds32(base);
                a[mi][1] = lds32(base + 8 * ROWB);
                a[mi][2] = lds32(base + 16);
                a[mi][3] = lds32(base + 8 * ROWB + 16);
            }
#pragma unroll
            for (int ni = 0; ni < 8; ++ni) {
                uint32_t base = bbase + (uint32_t)(wn * 64 + ni * 8 + g) * ROWB
                              + (uint32_t)(ko + tig * 2) * 2;
                b[ni][0] = lds32(base);
                b[ni][1] = lds32(base + 16);
            }
#pragma unroll
            for (int mi = 0; mi < 2; ++mi)
#pragma unroll
                for (int ni = 0; ni < 8; ++ni)
                    mma16816(acc[mi][ni], a[mi], b[ni]);
        }
        __syncthreads();
    }

    // ---- epilogue: D -> smem (padded), then fused leaky scan over t ----
    float* Ds = (float*)dynsm;                   // 128 x 132 floats = 67.6 KB
#pragma unroll
    for (int mi = 0; mi < 2; ++mi) {
        int row = wm * 32 + mi * 16 + g;
#pragma unroll
        for (int ni = 0; ni < 8; ++ni) {
            int col = wn * 64 + ni * 8 + tig * 2;
            *(float2*)&Ds[row * EPAD + col] = make_float2(acc[mi][ni][0], acc[mi][ni][1]);
            *(float2*)&Ds[(row + 8) * EPAD + col] = make_float2(acc[mi][ni][2], acc[mi][ni][3]);
        }
    }
    __syncthreads();

    int b_local = tid >> 7, hcol = tid & 127;
    int b = blockIdx.x * 2 + b_local;
    int h = n0 + hcol;
    float thr = *thr_p;
    float mem = 0.0f;
    for (int t = 0; t < TT; ++t) {
        float cur = Ds[(b_local * 64 + t) * EPAD + hcol];
        float reset = (mem > thr) ? thr : 0.0f;
        mem = 0.5f * mem + cur - reset;
        float spk = (mem - thr) > 0.0f ? 1.0f : 0.0f;
        size_t oidx = ((size_t)(t * BB + b)) * HH + h;
        spk0[oidx] = spk;
        mem0[oidx] = mem;
        unsigned bal = __ballot_sync(0xffffffffu, spk != 0.0f);
        if ((tid & 31) == 0) mask0[(size_t)(b * 64 + t) * 32 + (h >> 5)] = bal;
    }
}

// ================= build t-sorted event list per batch from mask0 ================
__global__ void k_build_events(const unsigned int* __restrict__ mask0,
                               unsigned int* __restrict__ ev, int* __restrict__ nev) {
    int warp = (blockIdx.x * blockDim.x + threadIdx.x) >> 5;   // warp = b
    int lane = threadIdx.x & 31;
    if (warp >= BB) return;
    int b = warp;
    int base = 0;
#pragma unroll
    for (int r = 0; r < 2; ++r) {
        int t = r * 32 + lane;
        const unsigned* mrow = mask0 + (size_t)(b * 64 + t) * 32;
        int cnt = 0;
#pragma unroll
        for (int w = 0; w < 32; ++w) cnt += __popc(mrow[w]);
        int incl = cnt;
        for (int d = 1; d < 32; d <<= 1) {
            int v = __shfl_up_sync(0xffffffffu, incl, d);
            if (lane >= d) incl += v;
        }
        int tot = __shfl_sync(0xffffffffu, incl, 31);
        int idx = base + incl - cnt;            // exclusive offset
#pragma unroll
        for (int w = 0; w < 32; ++w) {
            unsigned m = mrow[w];
            while (m) {
                int k = __ffs(m) - 1; m &= m - 1;
                if (idx < CAP) ev[(size_t)b * CAP + idx] = (unsigned)((t << 10) | (w * 32 + k));
                ++idx;
            }
        }
        base += tot;
    }
    if (lane == 0) nev[b] = base > CAP ? CAP : base;
}

// ================= layer 1: event-driven GEMM + scan, fully fused ================
__global__ __launch_bounds__(1024, 1)
void k_l1_fused(const unsigned int* __restrict__ ev, const int* __restrict__ nev,
                const float* __restrict__ W1t, const float* __restrict__ thr_p,
                float* __restrict__ spk1, float* __restrict__ mem1,
                unsigned int* __restrict__ mask1) {
    __shared__ unsigned int sev[CAP];
    __shared__ int sn;
    int b = blockIdx.x;
    int tid = threadIdx.x;                      // = h
    if (tid == 0) sn = nev[b];
    __syncthreads();
    int n = sn;
    for (int i = tid; i < n; i += 1024) sev[i] = ev[(size_t)b * CAP + i];
    __syncthreads();

    float thr = *thr_p;
    float mem = 0.0f;
    int ci = 0;
    for (int t = 0; t < TT; ++t) {
        float cur = 0.0f;
        while (ci < n && (int)(sev[ci] >> 10) == t) {
            int k = sev[ci] & 1023;
            cur += W1t[(size_t)k * HH + tid];
            ++ci;
        }
        float reset = (mem > thr) ? thr : 0.0f;
        mem = 0.5f * mem + cur - reset;
        float spk = (mem - thr) > 0.0f ? 1.0f : 0.0f;
        size_t oidx = ((size_t)(t * BB + b)) * HH + tid;
        spk1[oidx] = spk;
        mem1[oidx] = mem;
        unsigned bal = __ballot_sync(0xffffffffu, spk != 0.0f);
        if ((tid & 31) == 0) mask1[(size_t)(b * 64 + t) * 32 + (tid >> 5)] = bal;
    }
}

// ================= layer 2: mask-walk GEMM + scan (O=2) ==========================
__global__ void k_l2_fused(const unsigned int* __restrict__ mask1,
                           const float* __restrict__ W2, const float* __restrict__ thr_p,
                           float* __restrict__ spk2, float* __restrict__ mem2) {
    int b = blockIdx.x * blockDim.x + threadIdx.x;
    if (b >= BB) return;
    float thr = *thr_p;
    float ma = 0.0f, mb = 0.0f;
    for (int t = 0; t < TT; ++t) {
        float a0 = 0.0f, a1 = 0.0f;
        const unsigned* mw = mask1 + (size_t)(b * 64 + t) * 32;
        for (int w = 0; w < 32; ++w) {
            unsigned m = mw[w];
            while (m) {
                int k = __ffs(m) - 1; m &= m - 1;
                int kk = w * 32 + k;
                a0 += W2[kk];
                a1 += W2[HH + kk];
            }
        }
        float r0 = (ma > thr) ? thr : 0.0f;
        ma = 0.5f * ma + a0 - r0;
        float r1 = (mb > thr) ? thr : 0.0f;
        mb = 0.5f * mb + a1 - r1;
        int oidx = (t * BB + b) * 2;
        spk2[oidx]     = (ma - thr) > 0.0f ? 1.0f : 0.0f;
        spk2[oidx + 1] = (mb - thr) > 0.0f ? 1.0f : 0.0f;
        mem2[oidx]     = ma;
        mem2[oidx + 1] = mb;
    }
}

// ================= launch ========================================================
extern "C" void kernel_launch(void* const* d_in, const int* in_sizes, int n_in,
                              void* d_out, int out_size) {
    const float* x    = (const float*)d_in[0];
    const float* W0   = (const float*)d_in[1];
    const float* W1   = (const float*)d_in[2];
    const float* W2   = (const float*)d_in[3];
    const float* thr0 = (const float*)d_in[4];
    const float* thr1 = (const float*)d_in[5];
    const float* thr2 = (const float*)d_in[6];
    float* out = (float*)d_out;

    float *W1t;
    __nv_bfloat16 *Abf, *W0hi, *W0lo;
    unsigned int *mask0, *mask1, *ev;
    int* nev;
    cudaGetSymbolAddress((void**)&W1t,   g_W1t);
    cudaGetSymbolAddress((void**)&Abf,   g_Abf);
    cudaGetSymbolAddress((void**)&W0hi,  g_W0hi);
    cudaGetSymbolAddress((void**)&W0lo,  g_W0lo);
    cudaGetSymbolAddress((void**)&mask0, g_mask0);
    cudaGetSymbolAddress((void**)&mask1, g_mask1);
    cudaGetSymbolAddress((void**)&ev,    g_ev);
    cudaGetSymbolAddress((void**)&nev,   g_nev);

    const int gemm0_smem = 2 * BUFB;                            // 73,728 B
    cudaFuncSetAttribute(k_gemm0_fused,
                         cudaFuncAttributeMaxDynamicSharedMemorySize, gemm0_smem);

    // output layout: spk0, spk1, spk2, mem0, mem1, mem2
    float* spk0 = out;
    float* spk1 = spk0 + (size_t)NS * HH;
    float* spk2 = spk1 + (size_t)NS * HH;
    float* mem0 = spk2 + (size_t)NS * 2;
    float* mem1 = mem0 + (size_t)NS * HH;
    float* mem2 = mem1 + (size_t)NS * HH;

    // prep
    k_convA<<<(NS * IN / 4) / 256, 256>>>(x, Abf);
    k_splitW<<<(HH * IN) / 256, 256>>>(W0, W0hi, W0lo, HH * IN);
    k_transpose<<<dim3(HH/32, HH/32), dim3(32, 8)>>>(W1, W1t, HH, HH);

    // layer 0: fused tensor-core GEMM + scan (no cur0 roundtrip)
    k_gemm0_fused<<<dim3(NS/128, HH/128), 256, gemm0_smem>>>(
        Abf, W0hi, W0lo, thr0, spk0, mem0, mask0);

    // layer 1: event-driven fused (no cur1)
    k_build_events<<<32, 256>>>(mask0, ev, nev);
    k_l1_fused<<<BB, 1024>>>(ev, nev, W1t, thr1, spk1, mem1, mask1);

    // layer 2: fused
    k_l2_fused<<<8, 32>>>(mask1, W2, thr2, spk2, mem2);
}

// round 8
// speedup vs baseline: 1.8965x; 1.8965x over previous
#include <cuda_runtime.h>
#include <cuda_bf16.h>
#include <cstdint>

#define BB 256
#define TT 64
#define IN 512
#define HH 1024
#define NS (BB*TT)   /* 16384 samples, s = b*TT + t (natural x order) */
#define CAP 8192     /* event capacity per batch */

// ---------------- scratch (__device__ globals; no allocs allowed) ----------------
__device__ unsigned int g_mask0[NS*32];        // layer-0 spike bitmasks [s][32]
__device__ unsigned int g_mask1[NS*32];
__device__ unsigned int g_ev[(size_t)BB*CAP];  // per-b event list (t<<10|k), t-sorted
__device__ int g_nev[BB];
__device__ float g_cur2[NS*2];
__device__ __nv_bfloat16 g_Abf[(size_t)NS*IN]; // input spikes as bf16 [s][i]
__device__ __nv_bfloat16 g_W0hi[HH*IN];        // bf16 split of W0 [h][i]
__device__ __nv_bfloat16 g_W0lo[HH*IN];
__device__ float g_W1t[HH*HH];                 // W1^T : [1024][1024]

// ================= helpers =======================================================
__device__ __forceinline__ uint32_t smem_u32(const void* p) {
    uint32_t a;
    asm("{ .reg .u64 t; cvta.to.shared.u64 t, %1; cvt.u32.u64 %0, t; }" : "=r"(a) : "l"(p));
    return a;
}
__device__ __forceinline__ void cp_async16(uint32_t dst, const void* src) {
    asm volatile("cp.async.cg.shared.global [%0], [%1], 16;" :: "r"(dst), "l"(src));
}
__device__ __forceinline__ uint32_t lds32(uint32_t a) {
    uint32_t v;
    asm volatile("ld.shared.b32 %0, [%1];" : "=r"(v) : "r"(a));
    return v;
}
__device__ __forceinline__ void mma16816(float* c, const uint32_t* a, const uint32_t* b) {
    asm volatile(
        "mma.sync.aligned.m16n8k16.row.col.f32.bf16.bf16.f32 "
        "{%0,%1,%2,%3}, {%4,%5,%6,%7}, {%8,%9}, {%0,%1,%2,%3};"
        : "+f"(c[0]), "+f"(c[1]), "+f"(c[2]), "+f"(c[3])
        : "r"(a[0]), "r"(a[1]), "r"(a[2]), "r"(a[3]), "r"(b[0]), "r"(b[1]));
}

// ================= prep kernels ==================================================
__global__ void k_convA(const float* __restrict__ x, __nv_bfloat16* __restrict__ A) {
    size_t p = (size_t)blockIdx.x * blockDim.x + threadIdx.x;   // NS*IN/4 threads
    float4 v = *(const float4*)(x + p * 4);
    __nv_bfloat162 lo = __floats2bfloat162_rn(v.x, v.y);
    __nv_bfloat162 hi = __floats2bfloat162_rn(v.z, v.w);
    uint2 o; o.x = *(uint32_t*)&lo; o.y = *(uint32_t*)&hi;
    *(uint2*)(A + p * 4) = o;
}
__global__ void k_splitW(const float* __restrict__ W, __nv_bfloat16* __restrict__ Whi,
                         __nv_bfloat16* __restrict__ Wlo, int n) {
    int e = blockIdx.x * blockDim.x + threadIdx.x;
    if (e >= n) return;
    float w = W[e];
    __nv_bfloat16 h = __float2bfloat16(w);
    __nv_bfloat16 l = __float2bfloat16(w - __bfloat162float(h));
    Whi[e] = h; Wlo[e] = l;
}
__global__ void k_transpose(const float* __restrict__ in, float* __restrict__ out,
                            int R, int C) {
    __shared__ float tl[32][33];
    int c0 = blockIdx.x * 32, r0 = blockIdx.y * 32;
    int x = c0 + threadIdx.x;
    for (int j = 0; j < 32; j += 8) {
        int y = r0 + threadIdx.y + j;
        if (y < R && x < C) tl[threadIdx.y + j][threadIdx.x] = in[(size_t)y * C + x];
    }
    __syncthreads();
    int x2 = r0 + threadIdx.x;
    for (int j = 0; j < 32; j += 8) {
        int y2 = c0 + threadIdx.y + j;
        if (y2 < C && x2 < R) out[(size_t)y2 * R + x2] = tl[threadIdx.x][threadIdx.y + j];
    }
}

// ================= layer 0: fused HMMA GEMM + leaky scan =========================
#define KCH   64
#define LDAH  72
#define ROWB  (LDAH*2)                   /* 144 bytes */
#define TILEB (128*ROWB)                 /* 18432 B per operand tile */
#define BUFB  (2*TILEB)                  /* 36864 B per buffer */
#define EPAD  132                        /* padded epilogue row (floats) */

extern __shared__ char dynsm[];

__global__ __launch_bounds__(256, 2)
void k_gemm0_fused(const __nv_bfloat16* __restrict__ A,
                   const __nv_bfloat16* __restrict__ Whi,
                   const __nv_bfloat16* __restrict__ Wlo,
                   const float* __restrict__ thr_p,
                   float* __restrict__ spk0, float* __restrict__ mem0,
                   unsigned int* __restrict__ mask0) {
    int tid = threadIdx.x;
    int wid = tid >> 5, lane = tid & 31;
    int g = lane >> 2, tig = lane & 3;
    int wm = wid & 3, wn = wid >> 2;             // warp grid 4(M) x 2(N)
    int m0 = blockIdx.x * 128;
    int n0 = blockIdx.y * 128;

    uint32_t smb = smem_u32(dynsm);

    float acc[2][8][4];
#pragma unroll
    for (int mi = 0; mi < 2; ++mi)
#pragma unroll
        for (int ni = 0; ni < 8; ++ni)
#pragma unroll
            for (int r = 0; r < 4; ++r) acc[mi][ni][r] = 0.0f;

    auto stage = [&](int c, int buf) {
        const __nv_bfloat16* Wsrc = (c < 8) ? Whi : Wlo;
        int kcol = (c & 7) * KCH;
        uint32_t abase = smb + buf * BUFB;
        uint32_t bbase = abase + TILEB;
#pragma unroll
        for (int j = 0; j < 4; ++j) {
            int id = tid + j * 256;
            int row = id >> 3, seg = id & 7;
            cp_async16(abase + row * ROWB + seg * 16,
                       A + (size_t)(m0 + row) * IN + kcol + seg * 8);
            cp_async16(bbase + row * ROWB + seg * 16,
                       Wsrc + (size_t)(n0 + row) * IN + kcol + seg * 8);
        }
        asm volatile("cp.async.commit_group;" ::: "memory");
    };

    stage(0, 0);

    for (int c = 0; c < 16; ++c) {
        int buf = c & 1;
        if (c + 1 < 16) {
            stage(c + 1, buf ^ 1);
            asm volatile("cp.async.wait_group 1;" ::: "memory");
        } else {
            asm volatile("cp.async.wait_group 0;" ::: "memory");
        }
        __syncthreads();

        uint32_t abase = smb + buf * BUFB;
        uint32_t bbase = abase + TILEB;
#pragma unroll
        for (int kk = 0; kk < 4; ++kk) {
            int ko = kk * 16;
            uint32_t a[2][4], b[8][2];
#pragma unroll
            for (int mi = 0; mi < 2; ++mi) {
                uint32_t base = abase + (uint32_t)(wm * 32 + mi * 16 + g) * ROWB
                              + (uint32_t)(ko + tig * 2) * 2;
                a[mi][0] = lds32(base);
                a[mi][1] = lds32(base + 8 * ROWB);
                a[mi][2] = lds32(base + 16);
                a[mi][3] = lds32(base + 8 * ROWB + 16);
            }
#pragma unroll
            for (int ni = 0; ni < 8; ++ni) {
                uint32_t base = bbase + (uint32_t)(wn * 64 + ni * 8 + g) * ROWB
                              + (uint32_t)(ko + tig * 2) * 2;
                b[ni][0] = lds32(base);
                b[ni][1] = lds32(base + 16);
            }
#pragma unroll
            for (int mi = 0; mi < 2; ++mi)
#pragma unroll
                for (int ni = 0; ni < 8; ++ni)
                    mma16816(acc[mi][ni], a[mi], b[ni]);
        }
        __syncthreads();
    }

    // ---- epilogue: D -> smem (padded), then fused leaky scan over t ----
    float* Ds = (float*)dynsm;                   // 128 x 132 floats = 67.6 KB
#pragma unroll
    for (int mi = 0; mi < 2; ++mi) {
        int row = wm * 32 + mi * 16 + g;
#pragma unroll
        for (int ni = 0; ni < 8; ++ni) {
            int col = wn * 64 + ni * 8 + tig * 2;
            *(float2*)&Ds[row * EPAD + col] = make_float2(acc[mi][ni][0], acc[mi][ni][1]);
            *(float2*)&Ds[(row + 8) * EPAD + col] = make_float2(acc[mi][ni][2], acc[mi][ni][3]);
        }
    }
    __syncthreads();

    int b_local = tid >> 7, hcol = tid & 127;
    int b = blockIdx.x * 2 + b_local;
    int h = n0 + hcol;
    float thr = *thr_p;
    float mem = 0.0f;
    for (int t = 0; t < TT; ++t) {
        float cur = Ds[(b_local * 64 + t) * EPAD + hcol];
        float reset = (mem > thr) ? thr : 0.0f;
        mem = 0.5f * mem + cur - reset;
        float spk = (mem - thr) > 0.0f ? 1.0f : 0.0f;
        size_t oidx = ((size_t)(t * BB + b)) * HH + h;
        spk0[oidx] = spk;
        mem0[oidx] = mem;
        unsigned bal = __ballot_sync(0xffffffffu, spk != 0.0f);
        if ((tid & 31) == 0) mask0[(size_t)(b * 64 + t) * 32 + (h >> 5)] = bal;
    }
}

// ================= build t-sorted event list per batch from mask0 ================
__global__ void k_build_events(const unsigned int* __restrict__ mask0,
                               unsigned int* __restrict__ ev, int* __restrict__ nev) {
    int warp = (blockIdx.x * blockDim.x + threadIdx.x) >> 5;   // warp = b
    int lane = threadIdx.x & 31;
    if (warp >= BB) return;
    int b = warp;
    int base = 0;
#pragma unroll
    for (int r = 0; r < 2; ++r) {
        int t = r * 32 + lane;
        const unsigned* mrow = mask0 + (size_t)(b * 64 + t) * 32;
        int cnt = 0;
#pragma unroll
        for (int w = 0; w < 32; ++w) cnt += __popc(mrow[w]);
        int incl = cnt;
        for (int d = 1; d < 32; d <<= 1) {
            int v = __shfl_up_sync(0xffffffffu, incl, d);
            if (lane >= d) incl += v;
        }
        int tot = __shfl_sync(0xffffffffu, incl, 31);
        int idx = base + incl - cnt;            // exclusive offset
#pragma unroll
        for (int w = 0; w < 32; ++w) {
            unsigned m = mrow[w];
            while (m) {
                int k = __ffs(m) - 1; m &= m - 1;
                if (idx < CAP) ev[(size_t)b * CAP + idx] = (unsigned)((t << 10) | (w * 32 + k));
                ++idx;
            }
        }
        base += tot;
    }
    if (lane == 0) nev[b] = base > CAP ? CAP : base;
}

// ================= layer 1: event-driven GEMM + scan (b x h-half grid) ===========
__global__ __launch_bounds__(512, 2)
void k_l1_fused(const unsigned int* __restrict__ ev, const int* __restrict__ nev,
                const float* __restrict__ W1t, const float* __restrict__ thr_p,
                float* __restrict__ spk1, float* __restrict__ mem1,
                unsigned int* __restrict__ mask1) {
    __shared__ unsigned int sev[CAP];
    __shared__ int sn;
    int b = blockIdx.x;
    int h = blockIdx.y * 512 + threadIdx.x;
    if (threadIdx.x == 0) sn = nev[b];
    __syncthreads();
    int n = sn;
    for (int i = threadIdx.x; i < n; i += 512) sev[i] = ev[(size_t)b * CAP + i];
    __syncthreads();

    float thr = *thr_p;
    float mem = 0.0f;
    int ci = 0;
    for (int t = 0; t < TT; ++t) {
        float cur = 0.0f;
        while (ci < n && (int)(sev[ci] >> 10) == t) {
            int k = sev[ci] & 1023;
            cur += W1t[(size_t)k * HH + h];
            ++ci;
        }
        float reset = (mem > thr) ? thr : 0.0f;
        mem = 0.5f * mem + cur - reset;
        float spk = (mem - thr) > 0.0f ? 1.0f : 0.0f;
        size_t oidx = ((size_t)(t * BB + b)) * HH + h;
        spk1[oidx] = spk;
        mem1[oidx] = mem;
        unsigned bal = __ballot_sync(0xffffffffu, spk != 0.0f);
        if ((threadIdx.x & 31) == 0) mask1[(size_t)(b * 64 + t) * 32 + (h >> 5)] = bal;
    }
}

// ================= layer 2: parallel cur + tiny scan =============================
// phase a: one warp per sample s=(b*64+t); lane w walks mask word w
__global__ void k_l2_cur(const unsigned int* __restrict__ mask1,
                         const float* __restrict__ W2, float* __restrict__ cur2) {
    int s = (blockIdx.x * blockDim.x + threadIdx.x) >> 5;
    int lane = threadIdx.x & 31;
    if (s >= NS) return;
    unsigned m = mask1[(size_t)s * 32 + lane];
    float a0 = 0.0f, a1 = 0.0f;
    while (m) {
        int k = __ffs(m) - 1; m &= m - 1;
        int kk = lane * 32 + k;
        a0 += W2[kk];
        a1 += W2[HH + kk];
    }
#pragma unroll
    for (int d = 16; d > 0; d >>= 1) {
        a0 += __shfl_down_sync(0xffffffffu, a0, d);
        a1 += __shfl_down_sync(0xffffffffu, a1, d);
    }
    if (lane == 0) { cur2[s * 2] = a0; cur2[s * 2 + 1] = a1; }
}
// phase b: 256 threads, each scans its batch's 64 steps (2 outputs)
__global__ void k_l2_scan(const float* __restrict__ cur2, const float* __restrict__ thr_p,
                          float* __restrict__ spk2, float* __restrict__ mem2) {
    int b = blockIdx.x * blockDim.x + threadIdx.x;
    if (b >= BB) return;
    float thr = *thr_p;
    float ma = 0.0f, mb = 0.0f;
    for (int t = 0; t < TT; ++t) {
        int sidx = (b * 64 + t) * 2;
        float r0 = (ma > thr) ? thr : 0.0f;
        ma = 0.5f * ma + cur2[sidx] - r0;
        float r1 = (mb > thr) ? thr : 0.0f;
        mb = 0.5f * mb + cur2[sidx + 1] - r1;
        int oidx = (t * BB + b) * 2;
        spk2[oidx]     = (ma - thr) > 0.0f ? 1.0f : 0.0f;
        spk2[oidx + 1] = (mb - thr) > 0.0f ? 1.0f : 0.0f;
        mem2[oidx]     = ma;
        mem2[oidx + 1] = mb;
    }
}

// ================= launch ========================================================
extern "C" void kernel_launch(void* const* d_in, const int* in_sizes, int n_in,
                              void* d_out, int out_size) {
    const float* x    = (const float*)d_in[0];
    const float* W0   = (const float*)d_in[1];
    const float* W1   = (const float*)d_in[2];
    const float* W2   = (const float*)d_in[3];
    const float* thr0 = (const float*)d_in[4];
    const float* thr1 = (const float*)d_in[5];
    const float* thr2 = (const float*)d_in[6];
    float* out = (float*)d_out;

    float *W1t, *cur2;
    __nv_bfloat16 *Abf, *W0hi, *W0lo;
    unsigned int *mask0, *mask1, *ev;
    int* nev;
    cudaGetSymbolAddress((void**)&W1t,   g_W1t);
    cudaGetSymbolAddress((void**)&cur2,  g_cur2);
    cudaGetSymbolAddress((void**)&Abf,   g_Abf);
    cudaGetSymbolAddress((void**)&W0hi,  g_W0hi);
    cudaGetSymbolAddress((void**)&W0lo,  g_W0lo);
    cudaGetSymbolAddress((void**)&mask0, g_mask0);
    cudaGetSymbolAddress((void**)&mask1, g_mask1);
    cudaGetSymbolAddress((void**)&ev,    g_ev);
    cudaGetSymbolAddress((void**)&nev,   g_nev);

    const int gemm0_smem = 2 * BUFB;                            // 73,728 B
    cudaFuncSetAttribute(k_gemm0_fused,
                         cudaFuncAttributeMaxDynamicSharedMemorySize, gemm0_smem);

    // output layout: spk0, spk1, spk2, mem0, mem1, mem2
    float* spk0 = out;
    float* spk1 = spk0 + (size_t)NS * HH;
    float* spk2 = spk1 + (size_t)NS * HH;
    float* mem0 = spk2 + (size_t)NS * 2;
    float* mem1 = mem0 + (size_t)NS * HH;
    float* mem2 = mem1 + (size_t)NS * HH;

    // prep
    k_convA<<<(NS * IN / 4) / 256, 256>>>(x, Abf);
    k_splitW<<<(HH * IN) / 256, 256>>>(W0, W0hi, W0lo, HH * IN);
    k_transpose<<<dim3(HH/32, HH/32), dim3(32, 8)>>>(W1, W1t, HH, HH);

    // layer 0: fused tensor-core GEMM + scan
    k_gemm0_fused<<<dim3(NS/128, HH/128), 256, gemm0_smem>>>(
        Abf, W0hi, W0lo, thr0, spk0, mem0, mask0);

    // layer 1: event-driven fused
    k_build_events<<<32, 256>>>(mask0, ev, nev);
    k_l1_fused<<<dim3(BB, 2), 512>>>(ev, nev, W1t, thr1, spk1, mem1, mask1);

    // layer 2: parallel cur + tiny scan
    k_l2_cur<<<NS / 8, 256>>>(mask1, W2, cur2);
    k_l2_scan<<<1, 256>>>(cur2, thr2, spk2, mem2);
}

// round 9
// speedup vs baseline: 2.0903x; 1.1022x over previous
#include <cuda_runtime.h>
#include <cuda_bf16.h>
#include <cstdint>

#define BB 256
#define TT 64
#define IN 512
#define HH 1024
#define NS (BB*TT)   /* 16384 samples, s = b*TT + t (natural x order) */
#define CAP 8192     /* event capacity per batch */

// ---------------- scratch (__device__ globals; no allocs allowed) ----------------
__device__ unsigned int g_mask0[NS*32];        // layer-0 spike bitmasks [s][32]
__device__ unsigned int g_mask1[NS*32];
__device__ unsigned int g_ev[(size_t)BB*CAP];  // per-b event list (t<<10|k), t-sorted
__device__ int g_nev[BB];
__device__ float g_cur2[NS*2];
__device__ __nv_bfloat16 g_Abf[(size_t)NS*IN]; // input spikes as bf16 [s][i]
__device__ __nv_bfloat16 g_W0hi[HH*IN];        // bf16 split of W0 [h][i]
__device__ __nv_bfloat16 g_W0lo[HH*IN];
__device__ float g_W1t[HH*HH];                 // W1^T : [1024][1024]

// ================= helpers =======================================================
__device__ __forceinline__ uint32_t smem_u32(const void* p) {
    uint32_t a;
    asm("{ .reg .u64 t; cvta.to.shared.u64 t, %1; cvt.u32.u64 %0, t; }" : "=r"(a) : "l"(p));
    return a;
}
__device__ __forceinline__ void cp_async16(uint32_t dst, const void* src) {
    asm volatile("cp.async.cg.shared.global [%0], [%1], 16;" :: "r"(dst), "l"(src));
}
__device__ __forceinline__ void ldsm4(uint32_t* r, uint32_t addr) {
    asm volatile("ldmatrix.sync.aligned.m8n8.x4.shared.b16 {%0,%1,%2,%3}, [%4];"
                 : "=r"(r[0]), "=r"(r[1]), "=r"(r[2]), "=r"(r[3]) : "r"(addr));
}
__device__ __forceinline__ void mma16816(float* c, const uint32_t* a, const uint32_t* b) {
    asm volatile(
        "mma.sync.aligned.m16n8k16.row.col.f32.bf16.bf16.f32 "
        "{%0,%1,%2,%3}, {%4,%5,%6,%7}, {%8,%9}, {%0,%1,%2,%3};"
        : "+f"(c[0]), "+f"(c[1]), "+f"(c[2]), "+f"(c[3])
        : "r"(a[0]), "r"(a[1]), "r"(a[2]), "r"(a[3]), "r"(b[0]), "r"(b[1]));
}

// ================= prep kernels ==================================================
__global__ void k_convA(const float* __restrict__ x, __nv_bfloat16* __restrict__ A) {
    size_t p = (size_t)blockIdx.x * blockDim.x + threadIdx.x;   // NS*IN/4 threads
    float4 v = *(const float4*)(x + p * 4);
    __nv_bfloat162 lo = __floats2bfloat162_rn(v.x, v.y);
    __nv_bfloat162 hi = __floats2bfloat162_rn(v.z, v.w);
    uint2 o; o.x = *(uint32_t*)&lo; o.y = *(uint32_t*)&hi;
    *(uint2*)(A + p * 4) = o;
}
__global__ void k_splitW(const float* __restrict__ W, __nv_bfloat16* __restrict__ Whi,
                         __nv_bfloat16* __restrict__ Wlo, int n) {
    int e = blockIdx.x * blockDim.x + threadIdx.x;
    if (e >= n) return;
    float w = W[e];
    __nv_bfloat16 h = __float2bfloat16(w);
    __nv_bfloat16 l = __float2bfloat16(w - __bfloat162float(h));
    Whi[e] = h; Wlo[e] = l;
}
__global__ void k_transpose(const float* __restrict__ in, float* __restrict__ out,
                            int R, int C) {
    __shared__ float tl[32][33];
    int c0 = blockIdx.x * 32, r0 = blockIdx.y * 32;
    int x = c0 + threadIdx.x;
    for (int j = 0; j < 32; j += 8) {
        int y = r0 + threadIdx.y + j;
        if (y < R && x < C) tl[threadIdx.y + j][threadIdx.x] = in[(size_t)y * C + x];
    }
    __syncthreads();
    int x2 = r0 + threadIdx.x;
    for (int j = 0; j < 32; j += 8) {
        int y2 = c0 + threadIdx.y + j;
        if (y2 < C && x2 < R) out[(size_t)y2 * R + x2] = tl[threadIdx.x][threadIdx.y + j];
    }
}

// ================= layer 0: fused HMMA GEMM + leaky scan =========================
#define KCH   64
#define LDAH  72
#define ROWB  (LDAH*2)                   /* 144 bytes */
#define TILEB (128*ROWB)                 /* 18432 B per operand tile */
#define BUFB  (2*TILEB)                  /* 36864 B per buffer */
#define EPAD  132                        /* padded epilogue row (floats) */

extern __shared__ char dynsm[];

__global__ __launch_bounds__(256, 2)
void k_gemm0_fused(const __nv_bfloat16* __restrict__ A,
                   const __nv_bfloat16* __restrict__ Whi,
                   const __nv_bfloat16* __restrict__ Wlo,
                   const float* __restrict__ thr_p,
                   float* __restrict__ spk0, float* __restrict__ mem0,
                   unsigned int* __restrict__ mask0) {
    int tid = threadIdx.x;
    int wid = tid >> 5, lane = tid & 31;
    int g = lane >> 2, tig = lane & 3;
    int wm = wid & 3, wn = wid >> 2;             // warp grid 4(M) x 2(N)
    int m0 = blockIdx.x * 128;
    int n0 = blockIdx.y * 128;

    uint32_t smb = smem_u32(dynsm);

    // ldmatrix lane-address offsets (see fragment-mapping derivation)
    uint32_t off_a = (uint32_t)(lane & 15) * ROWB + (uint32_t)(lane >> 4) * 16;
    uint32_t off_b = ((uint32_t)(lane & 7) + (uint32_t)((lane >> 4) << 3)) * ROWB
                   + (uint32_t)((lane >> 3) & 1) * 16;

    float acc[2][8][4];
#pragma unroll
    for (int mi = 0; mi < 2; ++mi)
#pragma unroll
        for (int ni = 0; ni < 8; ++ni)
#pragma unroll
            for (int r = 0; r < 4; ++r) acc[mi][ni][r] = 0.0f;

    auto stage = [&](int c, int buf) {
        const __nv_bfloat16* Wsrc = (c < 8) ? Whi : Wlo;
        int kcol = (c & 7) * KCH;
        uint32_t abase = smb + buf * BUFB;
        uint32_t bbase = abase + TILEB;
#pragma unroll
        for (int j = 0; j < 4; ++j) {
            int id = tid + j * 256;
            int row = id >> 3, seg = id & 7;
            cp_async16(abase + row * ROWB + seg * 16,
                       A + (size_t)(m0 + row) * IN + kcol + seg * 8);
            cp_async16(bbase + row * ROWB + seg * 16,
                       Wsrc + (size_t)(n0 + row) * IN + kcol + seg * 8);
        }
        asm volatile("cp.async.commit_group;" ::: "memory");
    };

    stage(0, 0);

    for (int c = 0; c < 16; ++c) {
        int buf = c & 1;
        if (c + 1 < 16) {
            stage(c + 1, buf ^ 1);
            asm volatile("cp.async.wait_group 1;" ::: "memory");
        } else {
            asm volatile("cp.async.wait_group 0;" ::: "memory");
        }
        __syncthreads();

        uint32_t abase = smb + buf * BUFB;
        uint32_t bbase = abase + TILEB;
#pragma unroll
        for (int kk = 0; kk < 4; ++kk) {
            uint32_t ko2 = (uint32_t)(kk * 16) * 2;
            uint32_t a[2][4], bq[4][4];
#pragma unroll
            for (int mi = 0; mi < 2; ++mi)
                ldsm4(a[mi], abase + (uint32_t)(wm * 32 + mi * 16) * ROWB + ko2 + off_a);
#pragma unroll
            for (int np = 0; np < 4; ++np)
                ldsm4(bq[np], bbase + (uint32_t)(wn * 64 + np * 16) * ROWB + ko2 + off_b);
#pragma unroll
            for (int mi = 0; mi < 2; ++mi)
#pragma unroll
                for (int np = 0; np < 4; ++np) {
                    mma16816(acc[mi][np * 2],     a[mi], &bq[np][0]);
                    mma16816(acc[mi][np * 2 + 1], a[mi], &bq[np][2]);
                }
        }
        __syncthreads();
    }

    // ---- epilogue: D -> smem (padded), then fused leaky scan over t ----
    float* Ds = (float*)dynsm;                   // 128 x 132 floats = 67.6 KB
#pragma unroll
    for (int mi = 0; mi < 2; ++mi) {
        int row = wm * 32 + mi * 16 + g;
#pragma unroll
        for (int ni = 0; ni < 8; ++ni) {
            int col = wn * 64 + ni * 8 + tig * 2;
            *(float2*)&Ds[row * EPAD + col] = make_float2(acc[mi][ni][0], acc[mi][ni][1]);
            *(float2*)&Ds[(row + 8) * EPAD + col] = make_float2(acc[mi][ni][2], acc[mi][ni][3]);
        }
    }
    __syncthreads();

    int b_local = tid >> 7, hcol = tid & 127;
    int b = blockIdx.x * 2 + b_local;
    int h = n0 + hcol;
    float thr = *thr_p;
    float mem = 0.0f;
    for (int t = 0; t < TT; ++t) {
        float cur = Ds[(b_local * 64 + t) * EPAD + hcol];
        float reset = (mem > thr) ? thr : 0.0f;
        mem = 0.5f * mem + cur - reset;
        float spk = (mem - thr) > 0.0f ? 1.0f : 0.0f;
        size_t oidx = ((size_t)(t * BB + b)) * HH + h;
        spk0[oidx] = spk;
        mem0[oidx] = mem;
        unsigned bal = __ballot_sync(0xffffffffu, spk != 0.0f);
        if ((tid & 31) == 0) mask0[(size_t)(b * 64 + t) * 32 + (h >> 5)] = bal;
    }
}

// ================= build t-sorted event list per batch from mask0 ================
__global__ void k_build_events(const unsigned int* __restrict__ mask0,
                               unsigned int* __restrict__ ev, int* __restrict__ nev) {
    int warp = (blockIdx.x * blockDim.x + threadIdx.x) >> 5;   // warp = b
    int lane = threadIdx.x & 31;
    if (warp >= BB) return;
    int b = warp;
    int base = 0;
#pragma unroll
    for (int r = 0; r < 2; ++r) {
        int t = r * 32 + lane;
        const unsigned* mrow = mask0 + (size_t)(b * 64 + t) * 32;
        int cnt = 0;
#pragma unroll
        for (int w = 0; w < 32; ++w) cnt += __popc(mrow[w]);
        int incl = cnt;
        for (int d = 1; d < 32; d <<= 1) {
            int v = __shfl_up_sync(0xffffffffu, incl, d);
            if (lane >= d) incl += v;
        }
        int tot = __shfl_sync(0xffffffffu, incl, 31);
        int idx = base + incl - cnt;            // exclusive offset
#pragma unroll
        for (int w = 0; w < 32; ++w) {
            unsigned m = mrow[w];
            while (m) {
                int k = __ffs(m) - 1; m &= m - 1;
                if (idx < CAP) ev[(size_t)b * CAP + idx] = (unsigned)((t << 10) | (w * 32 + k));
                ++idx;
            }
        }
        base += tot;
    }
    if (lane == 0) nev[b] = base > CAP ? CAP : base;
}

// ================= layer 1: event-driven GEMM + scan (b x h-half grid) ===========
__global__ __launch_bounds__(512, 2)
void k_l1_fused(const unsigned int* __restrict__ ev, const int* __restrict__ nev,
                const float* __restrict__ W1t, const float* __restrict__ thr_p,
                float* __restrict__ spk1, float* __restrict__ mem1,
                unsigned int* __restrict__ mask1) {
    __shared__ unsigned int sev[CAP];
    __shared__ int sn;
    int b = blockIdx.x;
    int h = blockIdx.y * 512 + threadIdx.x;
    if (threadIdx.x == 0) sn = nev[b];
    __syncthreads();
    int n = sn;
    for (int i = threadIdx.x; i < n; i += 512) sev[i] = ev[(size_t)b * CAP + i];
    __syncthreads();

    float thr = *thr_p;
    float mem = 0.0f;
    int ci = 0;
    for (int t = 0; t < TT; ++t) {
        float cur = 0.0f;
        while (ci < n && (int)(sev[ci] >> 10) == t) {
            int k = sev[ci] & 1023;
            cur += W1t[(size_t)k * HH + h];
            ++ci;
        }
        float reset = (mem > thr) ? thr : 0.0f;
        mem = 0.5f * mem + cur - reset;
        float spk = (mem - thr) > 0.0f ? 1.0f : 0.0f;
        size_t oidx = ((size_t)(t * BB + b)) * HH + h;
        spk1[oidx] = spk;
        mem1[oidx] = mem;
        unsigned bal = __ballot_sync(0xffffffffu, spk != 0.0f);
        if ((threadIdx.x & 31) == 0) mask1[(size_t)(b * 64 + t) * 32 + (h >> 5)] = bal;
    }
}

// ================= layer 2: parallel cur + smem-staged scan ======================
__global__ void k_l2_cur(const unsigned int* __restrict__ mask1,
                         const float* __restrict__ W2, float* __restrict__ cur2) {
    int s = (blockIdx.x * blockDim.x + threadIdx.x) >> 5;
    int lane = threadIdx.x & 31;
    if (s >= NS) return;
    unsigned m = mask1[(size_t)s * 32 + lane];
    float a0 = 0.0f, a1 = 0.0f;
    while (m) {
        int k = __ffs(m) - 1; m &= m - 1;
        int kk = lane * 32 + k;
        a0 += W2[kk];
        a1 += W2[HH + kk];
    }
#pragma unroll
    for (int d = 16; d > 0; d >>= 1) {
        a0 += __shfl_down_sync(0xffffffffu, a0, d);
        a1 += __shfl_down_sync(0xffffffffu, a1, d);
    }
    if (lane == 0) { cur2[s * 2] = a0; cur2[s * 2 + 1] = a1; }
}
// 8 CTAs x 256 thr; CTA handles 32 batches: coalesced smem stage, then fast scan
__global__ void k_l2_scan(const float* __restrict__ cur2, const float* __restrict__ thr_p,
                          float* __restrict__ spk2, float* __restrict__ mem2) {
    __shared__ float sc[32 * TT * 2];            // 16 KB
    int b0 = blockIdx.x * 32;
    // coalesced load of this CTA's cur2 slice (4096 floats)
    const float* src = cur2 + (size_t)b0 * TT * 2;
    for (int i = threadIdx.x; i < 32 * TT * 2; i += 256) sc[i] = src[i];
    __syncthreads();
    if (threadIdx.x >= 32) return;
    int bl = threadIdx.x;
    int b = b0 + bl;
    float thr = *thr_p;
    float ma = 0.0f, mb = 0.0f;
    for (int t = 0; t < TT; ++t) {
        int sidx = (bl * TT + t) * 2;
        float r0 = (ma > thr) ? thr : 0.0f;
        ma = 0.5f * ma + sc[sidx] - r0;
        float r1 = (mb > thr) ? thr : 0.0f;
        mb = 0.5f * mb + sc[sidx + 1] - r1;
        int oidx = (t * BB + b) * 2;
        spk2[oidx]     = (ma - thr) > 0.0f ? 1.0f : 0.0f;
        spk2[oidx + 1] = (mb - thr) > 0.0f ? 1.0f : 0.0f;
        mem2[oidx]     = ma;
        mem2[oidx + 1] = mb;
    }
}

// ================= launch ========================================================
extern "C" void kernel_launch(void* const* d_in, const int* in_sizes, int n_in,
                              void* d_out, int out_size) {
    const float* x    = (const float*)d_in[0];
    const float* W0   = (const float*)d_in[1];
    const float* W1   = (const float*)d_in[2];
    const float* W2   = (const float*)d_in[3];
    const float* thr0 = (const float*)d_in[4];
    const float* thr1 = (const float*)d_in[5];
    const float* thr2 = (const float*)d_in[6];
    float* out = (float*)d_out;

    float *W1t, *cur2;
    __nv_bfloat16 *Abf, *W0hi, *W0lo;
    unsigned int *mask0, *mask1, *ev;
    int* nev;
    cudaGetSymbolAddress((void**)&W1t,   g_W1t);
    cudaGetSymbolAddress((void**)&cur2,  g_cur2);
    cudaGetSymbolAddress((void**)&Abf,   g_Abf);
    cudaGetSymbolAddress((void**)&W0hi,  g_W0hi);
    cudaGetSymbolAddress((void**)&W0lo,  g_W0lo);
    cudaGetSymbolAddress((void**)&mask0, g_mask0);
    cudaGetSymbolAddress((void**)&mask1, g_mask1);
    cudaGetSymbolAddress((void**)&ev,    g_ev);
    cudaGetSymbolAddress((void**)&nev,   g_nev);

    const int gemm0_smem = 2 * BUFB;                            // 73,728 B
    cudaFuncSetAttribute(k_gemm0_fused,
                         cudaFuncAttributeMaxDynamicSharedMemorySize, gemm0_smem);

    // output layout: spk0, spk1, spk2, mem0, mem1, mem2
    float* spk0 = out;
    float* spk1 = spk0 + (size_t)NS * HH;
    float* spk2 = spk1 + (size_t)NS * HH;
    float* mem0 = spk2 + (size_t)NS * 2;
    float* mem1 = mem0 + (size_t)NS * HH;
    float* mem2 = mem1 + (size_t)NS * HH;

    // prep
    k_convA<<<(NS * IN / 4) / 256, 256>>>(x, Abf);
    k_splitW<<<(HH * IN) / 256, 256>>>(W0, W0hi, W0lo, HH * IN);
    k_transpose<<<dim3(HH/32, HH/32), dim3(32, 8)>>>(W1, W1t, HH, HH);

    // layer 0: fused tensor-core GEMM + scan
    k_gemm0_fused<<<dim3(NS/128, HH/128), 256, gemm0_smem>>>(
        Abf, W0hi, W0lo, thr0, spk0, mem0, mask0);

    // layer 1: event-driven fused
    k_build_events<<<32, 256>>>(mask0, ev, nev);
    k_l1_fused<<<dim3(BB, 2), 512>>>(ev, nev, W1t, thr1, spk1, mem1, mask1);

    // layer 2: parallel cur + staged scan
    k_l2_cur<<<NS / 8, 256>>>(mask1, W2, cur2);
    k_l2_scan<<<8, 256>>>(cur2, thr2, spk2, mem2);
}

// round 13
// speedup vs baseline: 2.2364x; 1.0699x over previous
#include <cuda_runtime.h>
#include <cuda_bf16.h>
#include <cstdint>

#define BB 256
#define TT 64
#define IN 512
#define HH 1024
#define NS (BB*TT)   /* 16384 samples, s = b*TT + t (natural x order) */
#define CAP 8192     /* event capacity per batch */

// ---------------- scratch (__device__ globals; no allocs allowed) ----------------
__device__ unsigned int g_mask0[NS*32];        // layer-0 spike bitmasks [s][32]
__device__ unsigned int g_ev[(size_t)BB*CAP];  // per-b event list (t<<10|k), t-sorted
__device__ int g_nev[BB];
__device__ float g_cur2[NS*2];
__device__ __nv_bfloat16 g_Abf[(size_t)NS*IN]; // input spikes as bf16 [s][i]
__device__ __nv_bfloat16 g_W0hi[HH*IN];        // bf16 split of W0 [h][i]
__device__ __nv_bfloat16 g_W0lo[HH*IN];
__device__ float g_W1t[HH*HH];                 // W1^T : [1024][1024]

// ================= helpers =======================================================
__device__ __forceinline__ uint32_t smem_u32(const void* p) {
    uint32_t a;
    asm("{ .reg .u64 t; cvta.to.shared.u64 t, %1; cvt.u32.u64 %0, t; }" : "=r"(a) : "l"(p));
    return a;
}
__device__ __forceinline__ void cp_async16(uint32_t dst, const void* src) {
    asm volatile("cp.async.cg.shared.global [%0], [%1], 16;" :: "r"(dst), "l"(src));
}
__device__ __forceinline__ void ldsm4(uint32_t* r, uint32_t addr) {
    asm volatile("ldmatrix.sync.aligned.m8n8.x4.shared.b16 {%0,%1,%2,%3}, [%4];"
                 : "=r"(r[0]), "=r"(r[1]), "=r"(r[2]), "=r"(r[3]) : "r"(addr));
}
__device__ __forceinline__ void mma16816(float* c, const uint32_t* a, const uint32_t* b) {
    asm volatile(
        "mma.sync.aligned.m16n8k16.row.col.f32.bf16.bf16.f32 "
        "{%0,%1,%2,%3}, {%4,%5,%6,%7}, {%8,%9}, {%0,%1,%2,%3};"
        : "+f"(c[0]), "+f"(c[1]), "+f"(c[2]), "+f"(c[3])
        : "r"(a[0]), "r"(a[1]), "r"(a[2]), "r"(a[3]), "r"(b[0]), "r"(b[1]));
}

// ================= prep kernels ==================================================
__global__ void k_convA(const float* __restrict__ x, __nv_bfloat16* __restrict__ A) {
    size_t p = (size_t)blockIdx.x * blockDim.x + threadIdx.x;   // NS*IN/4 threads
    float4 v = *(const float4*)(x + p * 4);
    __nv_bfloat162 lo = __floats2bfloat162_rn(v.x, v.y);
    __nv_bfloat162 hi = __floats2bfloat162_rn(v.z, v.w);
    uint2 o; o.x = *(uint32_t*)&lo; o.y = *(uint32_t*)&hi;
    *(uint2*)(A + p * 4) = o;
}
__global__ void k_splitW(const float* __restrict__ W, __nv_bfloat16* __restrict__ Whi,
                         __nv_bfloat16* __restrict__ Wlo, int n) {
    int e = blockIdx.x * blockDim.x + threadIdx.x;
    if (e >= n) return;
    float w = W[e];
    __nv_bfloat16 h = __float2bfloat16(w);
    __nv_bfloat16 l = __float2bfloat16(w - __bfloat162float(h));
    Whi[e] = h; Wlo[e] = l;
}
__global__ void k_transpose(const float* __restrict__ in, float* __restrict__ out,
                            int R, int C) {
    __shared__ float tl[32][33];
    int c0 = blockIdx.x * 32, r0 = blockIdx.y * 32;
    int x = c0 + threadIdx.x;
    for (int j = 0; j < 32; j += 8) {
        int y = r0 + threadIdx.y + j;
        if (y < R && x < C) tl[threadIdx.y + j][threadIdx.x] = in[(size_t)y * C + x];
    }
    __syncthreads();
    int x2 = r0 + threadIdx.x;
    for (int j = 0; j < 32; j += 8) {
        int y2 = c0 + threadIdx.y + j;
        if (y2 < C && x2 < R) out[(size_t)y2 * R + x2] = tl[threadIdx.x][threadIdx.y + j];
    }
}

// ================= layer 0: fused HMMA GEMM + leaky scan =========================
// Per chunk stage {A, Bhi, Blo} once; run hi- and lo-MMAs off one A load.
#define KCH   64
#define LDAH  72
#define ROWB  (LDAH*2)                   /* 144 bytes */
#define TILEB (128*ROWB)                 /* 18432 B per operand tile */
#define BUFB  (3*TILEB)                  /* A + Bhi + Blo = 55296 B per buffer */
#define EPAD  132                        /* padded epilogue row (floats) */

extern __shared__ char dynsm[];

__global__ __launch_bounds__(256, 2)
void k_gemm0_fused(const __nv_bfloat16* __restrict__ A,
                   const __nv_bfloat16* __restrict__ Whi,
                   const __nv_bfloat16* __restrict__ Wlo,
                   const float* __restrict__ thr_p,
                   float* __restrict__ spk0, float* __restrict__ mem0,
                   unsigned int* __restrict__ mask0) {
    int tid = threadIdx.x;
    int wid = tid >> 5, lane = tid & 31;
    int g = lane >> 2, tig = lane & 3;
    int wm = wid & 3, wn = wid >> 2;             // warp grid 4(M) x 2(N)
    int m0 = blockIdx.x * 128;
    int n0 = blockIdx.y * 128;

    uint32_t smb = smem_u32(dynsm);

    uint32_t off_a = (uint32_t)(lane & 15) * ROWB + (uint32_t)(lane >> 4) * 16;
    uint32_t off_b = ((uint32_t)(lane & 7) + (uint32_t)((lane >> 4) << 3)) * ROWB
                   + (uint32_t)((lane >> 3) & 1) * 16;

    float acc[2][8][4];
#pragma unroll
    for (int mi = 0; mi < 2; ++mi)
#pragma unroll
        for (int ni = 0; ni < 8; ++ni)
#pragma unroll
            for (int r = 0; r < 4; ++r) acc[mi][ni][r] = 0.0f;

    auto stage = [&](int c, int buf) {
        int kcol = c * KCH;
        uint32_t abase = smb + buf * BUFB;
        uint32_t hbase = abase + TILEB;
        uint32_t lbase = hbase + TILEB;
#pragma unroll
        for (int j = 0; j < 4; ++j) {
            int id = tid + j * 256;              // 1024 16B-chunks per tile
            int row = id >> 3, seg = id & 7;
            uint32_t soff = row * ROWB + seg * 16;
            size_t goff = (size_t)row * IN + kcol + seg * 8;
            cp_async16(abase + soff, A   + (size_t)m0 * IN + goff);
            cp_async16(hbase + soff, Whi + (size_t)n0 * IN + goff);
            cp_async16(lbase + soff, Wlo + (size_t)n0 * IN + goff);
        }
        asm volatile("cp.async.commit_group;" ::: "memory");
    };

    stage(0, 0);

    for (int c = 0; c < 8; ++c) {
        int buf = c & 1;
        if (c + 1 < 8) {
            stage(c + 1, buf ^ 1);
            asm volatile("cp.async.wait_group 1;" ::: "memory");
        } else {
            asm volatile("cp.async.wait_group 0;" ::: "memory");
        }
        __syncthreads();

        uint32_t abase = smb + buf * BUFB;
#pragma unroll
        for (int kk = 0; kk < 4; ++kk) {
            uint32_t ko2 = (uint32_t)(kk * 16) * 2;
            uint32_t a[2][4];
#pragma unroll
            for (int mi = 0; mi < 2; ++mi)
                ldsm4(a[mi], abase + (uint32_t)(wm * 32 + mi * 16) * ROWB + ko2 + off_a);
#pragma unroll
            for (int p = 0; p < 2; ++p) {        // 0 = Whi, 1 = Wlo
                uint32_t bbase = abase + (1 + p) * TILEB;
                uint32_t bq[4][4];
#pragma unroll
                for (int np = 0; np < 4; ++np)
                    ldsm4(bq[np], bbase + (uint32_t)(wn * 64 + np * 16) * ROWB + ko2 + off_b);
#pragma unroll
                for (int mi = 0; mi < 2; ++mi)
#pragma unroll
                    for (int np = 0; np < 4; ++np) {
                        mma16816(acc[mi][np * 2],     a[mi], &bq[np][0]);
                        mma16816(acc[mi][np * 2 + 1], a[mi], &bq[np][2]);
                    }
            }
        }
        __syncthreads();
    }

    // ---- epilogue: D -> smem (padded), then fused leaky scan over t ----
    float* Ds = (float*)dynsm;                   // 128 x 132 floats = 67.6 KB
#pragma unroll
    for (int mi = 0; mi < 2; ++mi) {
        int row = wm * 32 + mi * 16 + g;
#pragma unroll
        for (int ni = 0; ni < 8; ++ni) {
            int col = wn * 64 + ni * 8 + tig * 2;
            *(float2*)&Ds[row * EPAD + col] = make_float2(acc[mi][ni][0], acc[mi][ni][1]);
            *(float2*)&Ds[(row + 8) * EPAD + col] = make_float2(acc[mi][ni][2], acc[mi][ni][3]);
        }
    }
    __syncthreads();

    int b_local = tid >> 7, hcol = tid & 127;
    int b = blockIdx.x * 2 + b_local;
    int h = n0 + hcol;
    float thr = *thr_p;
    float mem = 0.0f;
    for (int t = 0; t < TT; ++t) {
        float cur = Ds[(b_local * 64 + t) * EPAD + hcol];
        float reset = (mem > thr) ? thr : 0.0f;
        mem = 0.5f * mem + cur - reset;
        float spk = (mem - thr) > 0.0f ? 1.0f : 0.0f;
        size_t oidx = ((size_t)(t * BB + b)) * HH + h;
        spk0[oidx] = spk;
        mem0[oidx] = mem;
        unsigned bal = __ballot_sync(0xffffffffu, spk != 0.0f);
        if ((tid & 31) == 0) mask0[(size_t)(b * 64 + t) * 32 + (h >> 5)] = bal;
    }
}

// ================= build t-sorted event list per batch from mask0 ================
__global__ void k_build_events(const unsigned int* __restrict__ mask0,
                               unsigned int* __restrict__ ev, int* __restrict__ nev) {
    int warp = (blockIdx.x * blockDim.x + threadIdx.x) >> 5;   // warp = b
    int lane = threadIdx.x & 31;
    if (warp >= BB) return;
    int b = warp;
    int base = 0;
#pragma unroll
    for (int r = 0; r < 2; ++r) {
        int t = r * 32 + lane;
        const unsigned* mrow = mask0 + (size_t)(b * 64 + t) * 32;
        int cnt = 0;
#pragma unroll
        for (int w = 0; w < 32; ++w) cnt += __popc(mrow[w]);
        int incl = cnt;
        for (int d = 1; d < 32; d <<= 1) {
            int v = __shfl_up_sync(0xffffffffu, incl, d);
            if (lane >= d) incl += v;
        }
        int tot = __shfl_sync(0xffffffffu, incl, 31);
        int idx = base + incl - cnt;            // exclusive offset
#pragma unroll
        for (int w = 0; w < 32; ++w) {
            unsigned m = mrow[w];
            while (m) {
                int k = __ffs(m) - 1; m &= m - 1;
                if (idx < CAP) ev[(size_t)b * CAP + idx] = (unsigned)((t << 10) | (w * 32 + k));
                ++idx;
            }
        }
        base += tot;
    }
    if (lane == 0) nev[b] = base > CAP ? CAP : base;
}

// ================= layer 1: event-driven GEMM + scan; spikes feed cur2 ===========
__global__ __launch_bounds__(512, 2)
void k_l1_fused(const unsigned int* __restrict__ ev, const int* __restrict__ nev,
                const float* __restrict__ W1t, const float* __restrict__ W2,
                const float* __restrict__ thr_p,
                float* __restrict__ spk1, float* __restrict__ mem1,
                float* __restrict__ cur2) {
    __shared__ unsigned int sev[CAP];
    __shared__ int sn;
    int b = blockIdx.x;
    int h = blockIdx.y * 512 + threadIdx.x;
    if (threadIdx.x == 0) sn = nev[b];
    __syncthreads();
    int n = sn;
    for (int i = threadIdx.x; i < n; i += 512) sev[i] = ev[(size_t)b * CAP + i];
    __syncthreads();

    float thr = *thr_p;
    float mem = 0.0f;
    int ci = 0;
    for (int t = 0; t < TT; ++t) {
        float cur = 0.0f;
        while (ci < n && (int)(sev[ci] >> 10) == t) {
            int k = sev[ci] & 1023;
            cur += W1t[(size_t)k * HH + h];
            ++ci;
        }
        float reset = (mem > thr) ? thr : 0.0f;
        mem = 0.5f * mem + cur - reset;
        float spk = (mem - thr) > 0.0f ? 1.0f : 0.0f;
        size_t oidx = ((size_t)(t * BB + b)) * HH + h;
        spk1[oidx] = spk;
        mem1[oidx] = mem;
        if (spk != 0.0f) {                       // rare (~0.4 per (b,t))
            atomicAdd(&cur2[(b * TT + t) * 2],     W2[h]);
            atomicAdd(&cur2[(b * TT + t) * 2 + 1], W2[HH + h]);
        }
    }
}

// ================= layer 2: smem-staged scan =====================================
__global__ void k_l2_scan(const float* __restrict__ cur2, const float* __restrict__ thr_p,
                          float* __restrict__ spk2, float* __restrict__ mem2) {
    __shared__ float sc[32 * TT * 2];            // 16 KB
    int b0 = blockIdx.x * 32;
    const float* src = cur2 + (size_t)b0 * TT * 2;
    for (int i = threadIdx.x; i < 32 * TT * 2; i += 256) sc[i] = src[i];
    __syncthreads();
    if (threadIdx.x >= 32) return;
    int bl = threadIdx.x;
    int b = b0 + bl;
    float thr = *thr_p;
    float ma = 0.0f, mb = 0.0f;
    for (int t = 0; t < TT; ++t) {
        int sidx = (bl * TT + t) * 2;
        float r0 = (ma > thr) ? thr : 0.0f;
        ma = 0.5f * ma + sc[sidx] - r0;
        float r1 = (mb > thr) ? thr : 0.0f;
        mb = 0.5f * mb + sc[sidx + 1] - r1;
        int oidx = (t * BB + b) * 2;
        spk2[oidx]     = (ma - thr) > 0.0f ? 1.0f : 0.0f;
        spk2[oidx + 1] = (mb - thr) > 0.0f ? 1.0f : 0.0f;
        mem2[oidx]     = ma;
        mem2[oidx + 1] = mb;
    }
}

// ================= launch ========================================================
extern "C" void kernel_launch(void* const* d_in, const int* in_sizes, int n_in,
                              void* d_out, int out_size) {
    const float* x    = (const float*)d_in[0];
    const float* W0   = (const float*)d_in[1];
    const float* W1   = (const float*)d_in[2];
    const float* W2   = (const float*)d_in[3];
    const float* thr0 = (const float*)d_in[4];
    const float* thr1 = (const float*)d_in[5];
    const float* thr2 = (const float*)d_in[6];
    float* out = (float*)d_out;

    float *W1t, *cur2;
    __nv_bfloat16 *Abf, *W0hi, *W0lo;
    unsigned int *mask0, *ev;
    int* nev;
    cudaGetSymbolAddress((void**)&W1t,   g_W1t);
    cudaGetSymbolAddress((void**)&cur2,  g_cur2);
    cudaGetSymbolAddress((void**)&Abf,   g_Abf);
    cudaGetSymbolAddress((void**)&W0hi,  g_W0hi);
    cudaGetSymbolAddress((void**)&W0lo,  g_W0lo);
    cudaGetSymbolAddress((void**)&mask0, g_mask0);
    cudaGetSymbolAddress((void**)&ev,    g_ev);
    cudaGetSymbolAddress((void**)&nev,   g_nev);

    const int gemm0_smem = 2 * BUFB;                            // 110,592 B
    cudaFuncSetAttribute(k_gemm0_fused,
                         cudaFuncAttributeMaxDynamicSharedMemorySize, gemm0_smem);

    // output layout: spk0, spk1, spk2, mem0, mem1, mem2
    float* spk0 = out;
    float* spk1 = spk0 + (size_t)NS * HH;
    float* spk2 = spk1 + (size_t)NS * HH;
    float* mem0 = spk2 + (size_t)NS * 2;
    float* mem1 = mem0 + (size_t)NS * HH;
    float* mem2 = mem1 + (size_t)NS * HH;

    // prep (+ zero cur2 for the atomic accumulation)
    cudaMemsetAsync(cur2, 0, (size_t)NS * 2 * sizeof(float));
    k_convA<<<(NS * IN / 4) / 256, 256>>>(x, Abf);
    k_splitW<<<(HH * IN) / 256, 256>>>(W0, W0hi, W0lo, HH * IN);
    k_transpose<<<dim3(HH/32, HH/32), dim3(32, 8)>>>(W1, W1t, HH, HH);

    // layer 0: fused tensor-core GEMM + scan
    k_gemm0_fused<<<dim3(NS/128, HH/128), 256, gemm0_smem>>>(
        Abf, W0hi, W0lo, thr0, spk0, mem0, mask0);

    // layer 1: event-driven fused; spikes feed cur2 via atomics
    k_build_events<<<32, 256>>>(mask0, ev, nev);
    k_l1_fused<<<dim3(BB, 2), 512>>>(ev, nev, W1t, W2, thr1, spk1, mem1, cur2);

    // layer 2: staged scan
    k_l2_scan<<<8, 256>>>(cur2, thr2, spk2, mem2);
}

// round 17
// speedup vs baseline: 2.3042x; 1.0304x over previous
#include <cuda_runtime.h>
#include <cuda_bf16.h>
#include <cstdint>

#define BB 256
#define TT 64
#define IN 512
#define HH 1024
#define NS (BB*TT)   /* 16384 samples, s = b*TT + t (natural x order) */
#define CAP 4096     /* event capacity per batch (~150x expected ~26) */

// ---------------- scratch (__device__ globals; no allocs allowed) ----------------
__device__ unsigned int g_mask0[NS*32];        // layer-0 spike bitmasks [s][32]
__device__ unsigned int g_ev[(size_t)BB*CAP];  // per-b event list (t<<10|k), t-sorted
__device__ int g_nev[BB];
__device__ float g_cur2[NS*2];
__device__ __nv_bfloat16 g_Abf[(size_t)NS*IN]; // input spikes as bf16 [s][i]
__device__ __nv_bfloat16 g_W0hi[HH*IN];        // bf16 split of W0 [h][i]
__device__ __nv_bfloat16 g_W0lo[HH*IN];
__device__ float g_W1t[HH*HH];                 // W1^T : [1024][1024]

// ================= helpers =======================================================
__device__ __forceinline__ uint32_t smem_u32(const void* p) {
    uint32_t a;
    asm("{ .reg .u64 t; cvta.to.shared.u64 t, %1; cvt.u32.u64 %0, t; }" : "=r"(a) : "l"(p));
    return a;
}
__device__ __forceinline__ void cp_async16(uint32_t dst, const void* src) {
    asm volatile("cp.async.cg.shared.global [%0], [%1], 16;" :: "r"(dst), "l"(src));
}
__device__ __forceinline__ void ldsm4(uint32_t* r, uint32_t addr) {
    asm volatile("ldmatrix.sync.aligned.m8n8.x4.shared.b16 {%0,%1,%2,%3}, [%4];"
                 : "=r"(r[0]), "=r"(r[1]), "=r"(r[2]), "=r"(r[3]) : "r"(addr));
}
__device__ __forceinline__ void mma16816(float* c, const uint32_t* a, const uint32_t* b) {
    asm volatile(
        "mma.sync.aligned.m16n8k16.row.col.f32.bf16.bf16.f32 "
        "{%0,%1,%2,%3}, {%4,%5,%6,%7}, {%8,%9}, {%0,%1,%2,%3};"
        : "+f"(c[0]), "+f"(c[1]), "+f"(c[2]), "+f"(c[3])
        : "r"(a[0]), "r"(a[1]), "r"(a[2]), "r"(a[3]), "r"(b[0]), "r"(b[1]));
}

// ================= merged prep kernel ============================================
// blocks [0, 8192):   convA   — x fp32 -> Abf bf16 (4 elts/thread)
// blocks [8192,10240): splitW — W0 -> (hi, lo) bf16
// blocks [10240,11264): transpose W1 -> W1t (32x32 tile per block)
#define PREP_CONV_BLKS  8192
#define PREP_SPLIT_BLKS 2048
#define PREP_TRANS_BLKS 1024

__global__ void k_prep(const float* __restrict__ x, __nv_bfloat16* __restrict__ A,
                       const float* __restrict__ W0, __nv_bfloat16* __restrict__ Whi,
                       __nv_bfloat16* __restrict__ Wlo,
                       const float* __restrict__ W1, float* __restrict__ W1t) {
    __shared__ float tl[32][33];
    int bid = blockIdx.x;
    int tid = threadIdx.x;
    if (bid < PREP_CONV_BLKS) {
        size_t p = (size_t)bid * 256 + tid;
        float4 v = *(const float4*)(x + p * 4);
        __nv_bfloat162 lo = __floats2bfloat162_rn(v.x, v.y);
        __nv_bfloat162 hi = __floats2bfloat162_rn(v.z, v.w);
        uint2 o; o.x = *(uint32_t*)&lo; o.y = *(uint32_t*)&hi;
        *(uint2*)(A + p * 4) = o;
    } else if (bid < PREP_CONV_BLKS + PREP_SPLIT_BLKS) {
        int e = (bid - PREP_CONV_BLKS) * 256 + tid;
        float w = W0[e];
        __nv_bfloat16 h = __float2bfloat16(w);
        __nv_bfloat16 l = __float2bfloat16(w - __bfloat162float(h));
        Whi[e] = h; Wlo[e] = l;
    } else {
        int tb = bid - PREP_CONV_BLKS - PREP_SPLIT_BLKS;    // 0..1023
        int c0 = (tb & 31) * 32, r0 = (tb >> 5) * 32;
        int tx = tid & 31, ty = tid >> 5;                    // 32 x 8
        int xcol = c0 + tx;
        for (int j = 0; j < 32; j += 8) {
            int y = r0 + ty + j;
            tl[ty + j][tx] = W1[(size_t)y * HH + xcol];
        }
        __syncthreads();
        int x2 = r0 + tx;
        for (int j = 0; j < 32; j += 8) {
            int y2 = c0 + ty + j;
            W1t[(size_t)y2 * HH + x2] = tl[tx][ty + j];
        }
    }
}

// ================= layer 0: fused HMMA GEMM + leaky scan =========================
// Per chunk stage {A, Bhi, Blo} once; run hi- and lo-MMAs off one A load.
#define KCH   64
#define LDAH  72
#define ROWB  (LDAH*2)                   /* 144 bytes */
#define TILEB (128*ROWB)                 /* 18432 B per operand tile */
#define BUFB  (3*TILEB)                  /* A + Bhi + Blo = 55296 B per buffer */
#define EPAD  132                        /* padded epilogue row (floats) */

extern __shared__ char dynsm[];

__global__ __launch_bounds__(256, 2)
void k_gemm0_fused(const __nv_bfloat16* __restrict__ A,
                   const __nv_bfloat16* __restrict__ Whi,
                   const __nv_bfloat16* __restrict__ Wlo,
                   const float* __restrict__ thr_p,
                   float* __restrict__ spk0, float* __restrict__ mem0,
                   unsigned int* __restrict__ mask0) {
    int tid = threadIdx.x;
    int wid = tid >> 5, lane = tid & 31;
    int g = lane >> 2, tig = lane & 3;
    int wm = wid & 3, wn = wid >> 2;             // warp grid 4(M) x 2(N)
    int m0 = blockIdx.x * 128;
    int n0 = blockIdx.y * 128;

    uint32_t smb = smem_u32(dynsm);

    uint32_t off_a = (uint32_t)(lane & 15) * ROWB + (uint32_t)(lane >> 4) * 16;
    uint32_t off_b = ((uint32_t)(lane & 7) + (uint32_t)((lane >> 4) << 3)) * ROWB
                   + (uint32_t)((lane >> 3) & 1) * 16;

    float acc[2][8][4];
#pragma unroll
    for (int mi = 0; mi < 2; ++mi)
#pragma unroll
        for (int ni = 0; ni < 8; ++ni)
#pragma unroll
            for (int r = 0; r < 4; ++r) acc[mi][ni][r] = 0.0f;

    auto stage = [&](int c, int buf) {
        int kcol = c * KCH;
        uint32_t abase = smb + buf * BUFB;
        uint32_t hbase = abase + TILEB;
        uint32_t lbase = hbase + TILEB;
#pragma unroll
        for (int j = 0; j < 4; ++j) {
            int id = tid + j * 256;              // 1024 16B-chunks per tile
            int row = id >> 3, seg = id & 7;
            uint32_t soff = row * ROWB + seg * 16;
            size_t goff = (size_t)row * IN + kcol + seg * 8;
            cp_async16(abase + soff, A   + (size_t)m0 * IN + goff);
            cp_async16(hbase + soff, Whi + (size_t)n0 * IN + goff);
            cp_async16(lbase + soff, Wlo + (size_t)n0 * IN + goff);
        }
        asm volatile("cp.async.commit_group;" ::: "memory");
    };

    stage(0, 0);

    for (int c = 0; c < 8; ++c) {
        int buf = c & 1;
        if (c + 1 < 8) {
            stage(c + 1, buf ^ 1);
            asm volatile("cp.async.wait_group 1;" ::: "memory");
        } else {
            asm volatile("cp.async.wait_group 0;" ::: "memory");
        }
        __syncthreads();

        uint32_t abase = smb + buf * BUFB;
#pragma unroll
        for (int kk = 0; kk < 4; ++kk) {
            uint32_t ko2 = (uint32_t)(kk * 16) * 2;
            uint32_t a[2][4];
#pragma unroll
            for (int mi = 0; mi < 2; ++mi)
                ldsm4(a[mi], abase + (uint32_t)(wm * 32 + mi * 16) * ROWB + ko2 + off_a);
#pragma unroll
            for (int p = 0; p < 2; ++p) {        // 0 = Whi, 1 = Wlo
                uint32_t bbase = abase + (1 + p) * TILEB;
                uint32_t bq[4][4];
#pragma unroll
                for (int np = 0; np < 4; ++np)
                    ldsm4(bq[np], bbase + (uint32_t)(wn * 64 + np * 16) * ROWB + ko2 + off_b);
#pragma unroll
                for (int mi = 0; mi < 2; ++mi)
#pragma unroll
                    for (int np = 0; np < 4; ++np) {
                        mma16816(acc[mi][np * 2],     a[mi], &bq[np][0]);
                        mma16816(acc[mi][np * 2 + 1], a[mi], &bq[np][2]);
                    }
            }
        }
        __syncthreads();
    }

    // ---- epilogue: D -> smem (padded), then fused leaky scan over t ----
    float* Ds = (float*)dynsm;                   // 128 x 132 floats = 67.6 KB
#pragma unroll
    for (int mi = 0; mi < 2; ++mi) {
        int row = wm * 32 + mi * 16 + g;
#pragma unroll
        for (int ni = 0; ni < 8; ++ni) {
            int col = wn * 64 + ni * 8 + tig * 2;
            *(float2*)&Ds[row * EPAD + col] = make_float2(acc[mi][ni][0], acc[mi][ni][1]);
            *(float2*)&Ds[(row + 8) * EPAD + col] = make_float2(acc[mi][ni][2], acc[mi][ni][3]);
        }
    }
    __syncthreads();

    int b_local = tid >> 7, hcol = tid & 127;
    int b = blockIdx.x * 2 + b_local;
    int h = n0 + hcol;
    float thr = *thr_p;
    float mem = 0.0f;
    for (int t = 0; t < TT; ++t) {
        float cur = Ds[(b_local * 64 + t) * EPAD + hcol];
        float reset = (mem > thr) ? thr : 0.0f;
        mem = 0.5f * mem + cur - reset;
        float spk = (mem - thr) > 0.0f ? 1.0f : 0.0f;
        size_t oidx = ((size_t)(t * BB + b)) * HH + h;
        spk0[oidx] = spk;
        mem0[oidx] = mem;
        unsigned bal = __ballot_sync(0xffffffffu, spk != 0.0f);
        if ((tid & 31) == 0) mask0[(size_t)(b * 64 + t) * 32 + (h >> 5)] = bal;
    }
}

// ================= build t-sorted event list per batch from mask0 ================
__global__ void k_build_events(const unsigned int* __restrict__ mask0,
                               unsigned int* __restrict__ ev, int* __restrict__ nev) {
    int warp = (blockIdx.x * blockDim.x + threadIdx.x) >> 5;   // warp = b
    int lane = threadIdx.x & 31;
    if (warp >= BB) return;
    int b = warp;
    int base = 0;
#pragma unroll
    for (int r = 0; r < 2; ++r) {
        int t = r * 32 + lane;
        const unsigned* mrow = mask0 + (size_t)(b * 64 + t) * 32;
        int cnt = 0;
#pragma unroll
        for (int w = 0; w < 32; ++w) cnt += __popc(mrow[w]);
        int incl = cnt;
        for (int d = 1; d < 32; d <<= 1) {
            int v = __shfl_up_sync(0xffffffffu, incl, d);
            if (lane >= d) incl += v;
        }
        int tot = __shfl_sync(0xffffffffu, incl, 31);
        int idx = base + incl - cnt;            // exclusive offset
#pragma unroll
        for (int w = 0; w < 32; ++w) {
            unsigned m = mrow[w];
            while (m) {
                int k = __ffs(m) - 1; m &= m - 1;
                if (idx < CAP) ev[(size_t)b * CAP + idx] = (unsigned)((t << 10) | (w * 32 + k));
                ++idx;
            }
        }
        base += tot;
    }
    if (lane == 0) nev[b] = base > CAP ? CAP : base;
}

// ================= layer 1: event-driven GEMM + scan; spikes feed cur2 ===========
// grid (256 b, 4 h-quarters) x 256 threads -> 1024 CTAs, single wave
__global__ __launch_bounds__(256)
void k_l1_fused(const unsigned int* __restrict__ ev, const int* __restrict__ nev,
                const float* __restrict__ W1t, const float* __restrict__ W2,
                const float* __restrict__ thr_p,
                float* __restrict__ spk1, float* __restrict__ mem1,
                float* __restrict__ cur2) {
    __shared__ unsigned int sev[CAP];
    __shared__ int sn;
    int b = blockIdx.x;
    int h = blockIdx.y * 256 + threadIdx.x;
    if (threadIdx.x == 0) sn = nev[b];
    __syncthreads();
    int n = sn;
    for (int i = threadIdx.x; i < n; i += 256) sev[i] = ev[(size_t)b * CAP + i];
    __syncthreads();

    float thr = *thr_p;
    float mem = 0.0f;
    int ci = 0;
    for (int t = 0; t < TT; ++t) {
        float cur = 0.0f;
        while (ci < n && (int)(sev[ci] >> 10) == t) {
            int k = sev[ci] & 1023;
            cur += W1t[(size_t)k * HH + h];
            ++ci;
        }
        float reset = (mem > thr) ? thr : 0.0f;
        mem = 0.5f * mem + cur - reset;
        float spk = (mem - thr) > 0.0f ? 1.0f : 0.0f;
        size_t oidx = ((size_t)(t * BB + b)) * HH + h;
        spk1[oidx] = spk;
        mem1[oidx] = mem;
        if (spk != 0.0f) {                       // rare (~0.4 per (b,t))
            atomicAdd(&cur2[(b * TT + t) * 2],     W2[h]);
            atomicAdd(&cur2[(b * TT + t) * 2 + 1], W2[HH + h]);
        }
    }
}

// ================= layer 2: smem-staged scan =====================================
__global__ void k_l2_scan(const float* __restrict__ cur2, const float* __restrict__ thr_p,
                          float* __restrict__ spk2, float* __restrict__ mem2) {
    __shared__ float sc[32 * TT * 2];            // 16 KB
    int b0 = blockIdx.x * 32;
    const float* src = cur2 + (size_t)b0 * TT * 2;
    for (int i = threadIdx.x; i < 32 * TT * 2; i += 256) sc[i] = src[i];
    __syncthreads();
    if (threadIdx.x >= 32) return;
    int bl = threadIdx.x;
    int b = b0 + bl;
    float thr = *thr_p;
    float ma = 0.0f, mb = 0.0f;
    for (int t = 0; t < TT; ++t) {
        int sidx = (bl * TT + t) * 2;
        float r0 = (ma > thr) ? thr : 0.0f;
        ma = 0.5f * ma + sc[sidx] - r0;
        float r1 = (mb > thr) ? thr : 0.0f;
        mb = 0.5f * mb + sc[sidx + 1] - r1;
        int oidx = (t * BB + b) * 2;
        spk2[oidx]     = (ma - thr) > 0.0f ? 1.0f : 0.0f;
        spk2[oidx + 1] = (mb - thr) > 0.0f ? 1.0f : 0.0f;
        mem2[oidx]     = ma;
        mem2[oidx + 1] = mb;
    }
}

// ================= launch ========================================================
extern "C" void kernel_launch(void* const* d_in, const int* in_sizes, int n_in,
                              void* d_out, int out_size) {
    const float* x    = (const float*)d_in[0];
    const float* W0   = (const float*)d_in[1];
    const float* W1   = (const float*)d_in[2];
    const float* W2   = (const float*)d_in[3];
    const float* thr0 = (const float*)d_in[4];
    const float* thr1 = (const float*)d_in[5];
    const float* thr2 = (const float*)d_in[6];
    float* out = (float*)d_out;

    float *W1t, *cur2;
    __nv_bfloat16 *Abf, *W0hi, *W0lo;
    unsigned int *mask0, *ev;
    int* nev;
    cudaGetSymbolAddress((void**)&W1t,   g_W1t);
    cudaGetSymbolAddress((void**)&cur2,  g_cur2);
    cudaGetSymbolAddress((void**)&Abf,   g_Abf);
    cudaGetSymbolAddress((void**)&W0hi,  g_W0hi);
    cudaGetSymbolAddress((void**)&W0lo,  g_W0lo);
    cudaGetSymbolAddress((void**)&mask0, g_mask0);
    cudaGetSymbolAddress((void**)&ev,    g_ev);
    cudaGetSymbolAddress((void**)&nev,   g_nev);

    const int gemm0_smem = 2 * BUFB;                            // 110,592 B
    cudaFuncSetAttribute(k_gemm0_fused,
                         cudaFuncAttributeMaxDynamicSharedMemorySize, gemm0_smem);

    // output layout: spk0, spk1, spk2, mem0, mem1, mem2
    float* spk0 = out;
    float* spk1 = spk0 + (size_t)NS * HH;
    float* spk2 = spk1 + (size_t)NS * HH;
    float* mem0 = spk2 + (size_t)NS * 2;
    float* mem1 = mem0 + (size_t)NS * HH;
    float* mem2 = mem1 + (size_t)NS * HH;

    // prep (+ zero cur2 for the atomic accumulation)
    cudaMemsetAsync(cur2, 0, (size_t)NS * 2 * sizeof(float));
    k_prep<<<PREP_CONV_BLKS + PREP_SPLIT_BLKS + PREP_TRANS_BLKS, 256>>>(
        x, Abf, W0, W0hi, W0lo, W1, W1t);

    // layer 0: fused tensor-core GEMM + scan
    k_gemm0_fused<<<dim3(NS/128, HH/128), 256, gemm0_smem>>>(
        Abf, W0hi, W0lo, thr0, spk0, mem0, mask0);

    // layer 1: event-driven fused; spikes feed cur2 via atomics
    k_build_events<<<32, 256>>>(mask0, ev, nev);
    k_l1_fused<<<dim3(BB, 4), 256>>>(ev, nev, W1t, W2, thr1, spk1, mem1, cur2);

    // layer 2: staged scan
    k_l2_scan<<<8, 256>>>(cur2, thr2, spk2, mem2);
}